// round 7
// baseline (speedup 1.0000x reference)
#include <cuda_runtime.h>
#include <cstdint>

#define S_LEN   4096
#define NTASKS  256
#define NALGOS  64
#define WARM    192
#define CHUNK   256

// prep[a][s] = {T1w_s, BC_{s+1}, AC_{s+2}, TM3_s} for the D=3 deferred chain
__device__ __align__(16) float4 prep_buf[NALGOS * S_LEN];

__device__ __forceinline__ float rcpf(float x) {
    float y; asm("rcp.approx.f32 %0, %1;" : "=f"(y) : "f"(x)); return y;
}
__device__ __forceinline__ float tanhapx(float x) {
    float y; asm("tanh.approx.f32 %0, %1;" : "=f"(y) : "f"(x)); return y;
}

#define PACK64(u, lo, hi)   asm("mov.b64 %0, {%1, %2};" : "=l"(u) : "f"(lo), "f"(hi))
#define UNPACK64(lo, hi, u) asm("mov.b64 {%0, %1}, %2;" : "=f"(lo), "=f"(hi) : "l"(u))
#define MULX2(o, a, b)      asm("mul.rn.f32x2 %0, %1, %2;" : "=l"(o) : "l"(a), "l"(b))
#define FMAX2(o, a, b, c)   asm("fma.rn.f32x2 %0, %1, %2, %3;" : "=l"(o) : "l"(a), "l"(b), "l"(c))
#define LDG64(v, p) asm("ld.global.nc.b64 %0, [%1];" : "=l"(v) : "l"(p))

// ---------------------------------------------------------------------------
// Prep: coefficient packing for the deferred (D=3) chain.
// ---------------------------------------------------------------------------
__global__ void __launch_bounds__(128) idl_prep(
    const int* __restrict__ lx, const float* __restrict__ tm,
    const float* __restrict__ diff, const float* __restrict__ memA)
{
    const int a = blockIdx.x >> 5;
    const int s = ((blockIdx.x & 31) << 7) + threadIdx.x;
    const float mem = memA[a];

    const int t0 = __ldg(lx + s);
    const int t1 = __ldg(lx + min(s + 1, S_LEN - 1));
    const int t2 = __ldg(lx + min(s + 2, S_LEN - 1));
    const int t3 = __ldg(lx + min(s + 3, S_LEN - 1));

    const float wh1 = 0.5f * rcpf(__ldg(diff + t1));
    const float wh2 = 0.5f * rcpf(__ldg(diff + t2));
    const float wh3 = 0.5f * rcpf(__ldg(diff + t3));

    float4 o;
    o.x = __ldg(tm + t0 * NTASKS + t1) * wh1;
    o.y = __ldg(tm + t0 * NTASKS + t2) * (wh2 * mem);
    o.z = wh3 * mem * mem;
    o.w = __ldg(tm + t0 * NTASKS + t3);
    prep_buf[a * S_LEN + s] = o;
}

// ---------------------------------------------------------------------------
// Main: 256 blocks = 64 algos x 4 block-chunks. Each warp runs the k-chain
// for its own chunk (4 chains/block, no idle warps), dumping the full 256-col
// res state at the warm/main seam. Phase 2 starts from that seed (no redundant
// warm-up), computes tanh and does transposed coalesced stores.
// ---------------------------------------------------------------------------
__global__ void __launch_bounds__(128) idl_main(
    const int*   __restrict__ lx,
    const float* __restrict__ tm,
    const float* __restrict__ diff,
    const float* __restrict__ effA,
    const float* __restrict__ memA,
    const float* __restrict__ boostA,
    float*       __restrict__ out)
{
    __shared__ float    kf_sh[4][CHUNK];          // k for main region, per chunk
    __shared__ float    res_sh[4][NTASKS];        // res seed at s0, per chunk
    __shared__ uint16_t t16_sh[4 * CHUNK];        // t*256 for block's s-range
    __shared__ __align__(16) float sbuf[4][16][66];

    const int b    = blockIdx.x;
    const int a    = b >> 2;
    const int blk4 = b & 3;
    const int tid  = threadIdx.x;
    const int w    = tid >> 5;
    const int lane = tid & 31;

    const float mem   = memA[a];
    const float eff   = effA[a];
    const float boost = boostA[a];

    // stage t-indices for the block's phase-2 range [blk4*1024, +1024)
    #pragma unroll
    for (int i = tid; i < 4 * CHUNK; i += 128)
        t16_sh[i] = (uint16_t)(__ldg(lx + blk4 * (4 * CHUNK) + i) << 8);

    // ================= PHASE 1: one chain per warp =================
    {
        const int q      = blk4 * 4 + w;          // global chunk 0..15
        const int warm_n = q ? WARM : 0;
        const int s0     = q * CHUNK;
        const int s_base = s0 - warm_n;

        uint64_t uu0 = 0, uu1 = 0, uu2 = 0, uu3 = 0;   // res cols lane*8+0..7
        uint64_t memm; PACK64(memm, mem, mem);

        ulonglong2 rA[4], rB[4];
        #pragma unroll
        for (int i = 0; i < 4; i++) {
            const int t = __ldg(lx + min(s_base + i, S_LEN - 1));
            const ulonglong2* rp = (const ulonglong2*)(tm + t * NTASKS + lane * 8);
            rA[i] = rp[0];
            rB[i] = rp[1];
        }
        const float4* prp = prep_buf + a * S_LEN;
        float4 PF[8];
        #pragma unroll
        for (int i = 0; i < 8; i++)
            PF[i] = __ldg(prp + min(s_base + i, S_LEN - 1));

        float g = 0.0f, base = 0.0f, pb1 = 0.0f, Am = 0.0f;
        float kq[4];

        // ---- warm region (no k output) ----
        for (int ib = 0; ib < warm_n; ib += 16) {
            #pragma unroll
            for (int u = 0; u < 16; u++) {
                const int s = s_base + ib + u;
                const float4 pf = PF[u & 7];

                float k   = fmaf(boost, g, eff);
                float arg = fmaf(k, pf.x, base);
                g = tanhapx(arg);

                base = fmaf(k, pf.y, pb1);
                float inner = fmaf(k, pf.w, Am);
                pb1 = pf.z * inner;

                uint64_t kk; PACK64(kk, k, k);
                uint64_t p0, p1, p2, p3;
                MULX2(p0, rA[u & 3].x, kk); FMAX2(uu0, uu0, memm, p0);
                MULX2(p1, rA[u & 3].y, kk); FMAX2(uu1, uu1, memm, p1);
                MULX2(p2, rB[u & 3].x, kk); FMAX2(uu2, uu2, memm, p2);
                MULX2(p3, rB[u & 3].y, kk); FMAX2(uu3, uu3, memm, p3);

                const int cn = __ldg(lx + min(s + 4, S_LEN - 1));
                uint64_t sA = (cn & 2) ? uu1 : uu0;
                uint64_t sB = (cn & 2) ? uu3 : uu2;
                uint64_t sv = (cn & 4) ? sB : sA;
                float lo, hi; UNPACK64(lo, hi, sv);
                float v  = (cn & 1) ? hi : lo;
                float bc = __shfl_sync(0xffffffffu, v, cn >> 3);
                Am = mem * bc;

                const ulonglong2* rp = (const ulonglong2*)(tm + cn * NTASKS + lane * 8);
                rA[u & 3] = rp[0];
                rB[u & 3] = rp[1];
                PF[u & 7] = __ldg(prp + min(s + 8, S_LEN - 1));
            }
        }

        // ---- dump res seed (state after step s0-1) ----
        {
            ulonglong2* rs = (ulonglong2*)&res_sh[w][lane * 8];
            ulonglong2 d0; d0.x = uu0; d0.y = uu1;
            ulonglong2 d1; d1.x = uu2; d1.y = uu3;
            rs[0] = d0;
            rs[1] = d1;
        }

        // ---- main region (emit k) ----
        for (int ib = warm_n; ib < warm_n + CHUNK; ib += 16) {
            #pragma unroll
            for (int u = 0; u < 16; u++) {
                const int i = ib + u;
                const int s = s_base + i;
                const float4 pf = PF[u & 7];

                float k   = fmaf(boost, g, eff);
                float arg = fmaf(k, pf.x, base);
                g = tanhapx(arg);

                kq[u & 3] = k;
                if ((u & 3) == 3 && lane == 0)
                    *(float4*)&kf_sh[w][i - warm_n - 3] =
                        make_float4(kq[0], kq[1], kq[2], kq[3]);

                base = fmaf(k, pf.y, pb1);
                float inner = fmaf(k, pf.w, Am);
                pb1 = pf.z * inner;

                uint64_t kk; PACK64(kk, k, k);
                uint64_t p0, p1, p2, p3;
                MULX2(p0, rA[u & 3].x, kk); FMAX2(uu0, uu0, memm, p0);
                MULX2(p1, rA[u & 3].y, kk); FMAX2(uu1, uu1, memm, p1);
                MULX2(p2, rB[u & 3].x, kk); FMAX2(uu2, uu2, memm, p2);
                MULX2(p3, rB[u & 3].y, kk); FMAX2(uu3, uu3, memm, p3);

                const int cn = __ldg(lx + min(s + 4, S_LEN - 1));
                uint64_t sA = (cn & 2) ? uu1 : uu0;
                uint64_t sB = (cn & 2) ? uu3 : uu2;
                uint64_t sv = (cn & 4) ? sB : sA;
                float lo, hi; UNPACK64(lo, hi, sv);
                float v  = (cn & 1) ? hi : lo;
                float bc = __shfl_sync(0xffffffffu, v, cn >> 3);
                Am = mem * bc;

                const ulonglong2* rp = (const ulonglong2*)(tm + cn * NTASKS + lane * 8);
                rA[u & 3] = rp[0];
                rB[u & 3] = rp[1];
                PF[u & 7] = __ldg(prp + min(s + 8, S_LEN - 1));
            }
        }
    }
    __syncthreads();

    // ================= PHASE 2: seeded columns, 4 chunks =================
    const int c0 = w * 64 + 2 * lane;               // this thread's col pair
    const float wh0 = 0.5f * rcpf(__ldg(diff + c0));
    const float wh1 = 0.5f * rcpf(__ldg(diff + c0 + 1));
    uint64_t memm2; PACK64(memm2, mem, mem);

    #pragma unroll 1
    for (int cq = 0; cq < 4; cq++) {
        const int qq  = blk4 * 4 + cq;
        const int s0q = qq * CHUNK;

        const float2 seed = *(const float2*)&res_sh[cq][c0];
        uint64_t rr; PACK64(rr, seed.x, seed.y);

        #pragma unroll 1
        for (int tile = 0; tile < CHUNK / 16; tile++) {
            #pragma unroll
            for (int j = 0; j < 16; j++) {
                const int idx = tile * 16 + j;
                const uint32_t toff = (uint32_t)t16_sh[cq * CHUNK + idx];
                uint64_t tv; LDG64(tv, (const void*)(tm + toff + c0));
                const float kv = kf_sh[cq][idx];
                uint64_t kk; PACK64(kk, kv, kv);
                uint64_t pr; MULX2(pr, tv, kk);
                FMAX2(rr, rr, memm2, pr);
                float lo, hi; UNPACK64(lo, hi, rr);
                float2 pair = make_float2(tanhapx(lo * wh0), tanhapx(hi * wh1));
                *(float2*)&sbuf[w][j][2 * lane] = pair;
            }
            __syncwarp();
            #pragma unroll
            for (int i2 = 0; i2 < 32; i2++) {
                const int cl = 2 * i2 + (lane >> 4);    // local col 0..63
                const int j  = lane & 15;
                const float v = sbuf[w][j][cl];
                out[(size_t)(a * NTASKS + w * 64 + cl) * (size_t)(S_LEN + 1)
                    + 1 + s0q + tile * 16 + j] = v;
            }
            __syncwarp();
        }
    }

    // zero output column 0 (once per algo)
    if (blk4 == 0) {
        for (int c = tid; c < NTASKS; c += 128)
            out[(size_t)(a * NTASKS + c) * (size_t)(S_LEN + 1)] = 0.0f;
    }
}

extern "C" void kernel_launch(void* const* d_in, const int* in_sizes, int n_in,
                              void* d_out, int out_size)
{
    (void)in_sizes; (void)n_in; (void)out_size;
    const int*   lx    = (const int*)  d_in[0];
    const float* tm    = (const float*)d_in[1];
    const float* diff  = (const float*)d_in[2];
    const float* eff   = (const float*)d_in[3];
    const float* mem   = (const float*)d_in[4];
    const float* boost = (const float*)d_in[5];
    float*       out   = (float*)d_out;

    idl_prep<<<NALGOS * 32, 128>>>(lx, tm, diff, mem);
    idl_main<<<NALGOS * 4, 128>>>(lx, tm, diff, eff, mem, boost, out);
}

// round 8
// speedup vs baseline: 1.0605x; 1.0605x over previous
#include <cuda_runtime.h>
#include <cstdint>

#define S_LEN   4096
#define NTASKS  256
#define NALGOS  64
#define WARM    192
#define CHUNK   256
#define NCHUNK  16

// prep[a][s] = {T1w_s, BC_{s+1}, AC_{s+2}, TM3_s} for the D=3 deferred chain
__device__ __align__(16) float4 prep_buf[NALGOS * S_LEN];
// handoff: per (a,chunk) k-values and res seed at the chunk seam
__device__ __align__(16) float k_glob[NALGOS * NCHUNK][CHUNK];
__device__ __align__(16) float seed_glob[NALGOS * NCHUNK][NTASKS];

__device__ __forceinline__ float rcpf(float x) {
    float y; asm("rcp.approx.f32 %0, %1;" : "=f"(y) : "f"(x)); return y;
}
__device__ __forceinline__ float tanhapx(float x) {
    float y; asm("tanh.approx.f32 %0, %1;" : "=f"(y) : "f"(x)); return y;
}

#define PACK64(u, lo, hi)   asm("mov.b64 %0, {%1, %2};" : "=l"(u) : "f"(lo), "f"(hi))
#define UNPACK64(lo, hi, u) asm("mov.b64 {%0, %1}, %2;" : "=f"(lo), "=f"(hi) : "l"(u))
#define MULX2(o, a, b)      asm("mul.rn.f32x2 %0, %1, %2;" : "=l"(o) : "l"(a), "l"(b))
#define FMAX2(o, a, b, c)   asm("fma.rn.f32x2 %0, %1, %2, %3;" : "=l"(o) : "l"(a), "l"(b), "l"(c))
#define LDG64(v, p) asm("ld.global.nc.b64 %0, [%1];" : "=l"(v) : "l"(p))

// ---------------------------------------------------------------------------
// Prep: coefficient packing for the deferred (D=3) chain.
// ---------------------------------------------------------------------------
__global__ void __launch_bounds__(128) idl_prep(
    const int* __restrict__ lx, const float* __restrict__ tm,
    const float* __restrict__ diff, const float* __restrict__ memA)
{
    const int a = blockIdx.x >> 5;
    const int s = ((blockIdx.x & 31) << 7) + threadIdx.x;
    const float mem = memA[a];

    const int t0 = __ldg(lx + s);
    const int t1 = __ldg(lx + min(s + 1, S_LEN - 1));
    const int t2 = __ldg(lx + min(s + 2, S_LEN - 1));
    const int t3 = __ldg(lx + min(s + 3, S_LEN - 1));

    const float wh1 = 0.5f * rcpf(__ldg(diff + t1));
    const float wh2 = 0.5f * rcpf(__ldg(diff + t2));
    const float wh3 = 0.5f * rcpf(__ldg(diff + t3));

    float4 o;
    o.x = __ldg(tm + t0 * NTASKS + t1) * wh1;
    o.y = __ldg(tm + t0 * NTASKS + t2) * (wh2 * mem);
    o.z = wh3 * mem * mem;
    o.w = __ldg(tm + t0 * NTASKS + t3);
    prep_buf[a * S_LEN + s] = o;
}

// ---------------------------------------------------------------------------
// Chain: 1024 blocks x 32 threads, one k-chain per warp.
// Runs [s0-WARM, s0+CHUNK) from zero state; emits k for the main region and
// the full 256-col res state at the seam to global handoff buffers.
// ---------------------------------------------------------------------------
__global__ void __launch_bounds__(32) idl_chain(
    const int*   __restrict__ lx,
    const float* __restrict__ tm,
    const float* __restrict__ effA,
    const float* __restrict__ memA,
    const float* __restrict__ boostA)
{
    const int b    = blockIdx.x;
    const int a    = b >> 4;
    const int q    = b & 15;
    const int lane = threadIdx.x;

    const float mem   = memA[a];
    const float eff   = effA[a];
    const float boost = boostA[a];

    const int warm_n = q ? WARM : 0;
    const int s0     = q * CHUNK;
    const int s_base = s0 - warm_n;

    uint64_t uu0 = 0, uu1 = 0, uu2 = 0, uu3 = 0;   // res cols lane*8+0..7
    uint64_t memm; PACK64(memm, mem, mem);

    ulonglong2 rA[4], rB[4];
    #pragma unroll
    for (int i = 0; i < 4; i++) {
        const int t = __ldg(lx + min(s_base + i, S_LEN - 1));
        const ulonglong2* rp = (const ulonglong2*)(tm + t * NTASKS + lane * 8);
        rA[i] = rp[0];
        rB[i] = rp[1];
    }
    const float4* prp = prep_buf + a * S_LEN;
    float4 PF[8];
    #pragma unroll
    for (int i = 0; i < 8; i++)
        PF[i] = __ldg(prp + min(s_base + i, S_LEN - 1));

    float g = 0.0f, base = 0.0f, pb1 = 0.0f, Am = 0.0f;
    float kq[4];

    // ---- warm region ----
    for (int ib = 0; ib < warm_n; ib += 16) {
        #pragma unroll
        for (int u = 0; u < 16; u++) {
            const int s = s_base + ib + u;
            const float4 pf = PF[u & 7];

            float k   = fmaf(boost, g, eff);
            float arg = fmaf(k, pf.x, base);
            g = tanhapx(arg);

            base = fmaf(k, pf.y, pb1);
            float inner = fmaf(k, pf.w, Am);
            pb1 = pf.z * inner;

            uint64_t kk; PACK64(kk, k, k);
            uint64_t p0, p1, p2, p3;
            MULX2(p0, rA[u & 3].x, kk); FMAX2(uu0, uu0, memm, p0);
            MULX2(p1, rA[u & 3].y, kk); FMAX2(uu1, uu1, memm, p1);
            MULX2(p2, rB[u & 3].x, kk); FMAX2(uu2, uu2, memm, p2);
            MULX2(p3, rB[u & 3].y, kk); FMAX2(uu3, uu3, memm, p3);

            const int cn = __ldg(lx + min(s + 4, S_LEN - 1));
            uint64_t sA = (cn & 2) ? uu1 : uu0;
            uint64_t sB = (cn & 2) ? uu3 : uu2;
            uint64_t sv = (cn & 4) ? sB : sA;
            float lo, hi; UNPACK64(lo, hi, sv);
            float v  = (cn & 1) ? hi : lo;
            float bc = __shfl_sync(0xffffffffu, v, cn >> 3);
            Am = mem * bc;

            const ulonglong2* rp = (const ulonglong2*)(tm + cn * NTASKS + lane * 8);
            rA[u & 3] = rp[0];
            rB[u & 3] = rp[1];
            PF[u & 7] = __ldg(prp + min(s + 8, S_LEN - 1));
        }
    }

    // ---- dump res seed (state after step s0-1), coalesced 32B/lane ----
    {
        ulonglong2* rs = (ulonglong2*)&seed_glob[b][lane * 8];
        ulonglong2 d0; d0.x = uu0; d0.y = uu1;
        ulonglong2 d1; d1.x = uu2; d1.y = uu3;
        rs[0] = d0;
        rs[1] = d1;
    }

    // ---- main region (emit k) ----
    float* kout = k_glob[b];
    for (int ib = warm_n; ib < warm_n + CHUNK; ib += 16) {
        #pragma unroll
        for (int u = 0; u < 16; u++) {
            const int i = ib + u;
            const int s = s_base + i;
            const float4 pf = PF[u & 7];

            float k   = fmaf(boost, g, eff);
            float arg = fmaf(k, pf.x, base);
            g = tanhapx(arg);

            kq[u & 3] = k;
            if ((u & 3) == 3 && lane == 0)
                *(float4*)(kout + (i - warm_n - 3)) =
                    make_float4(kq[0], kq[1], kq[2], kq[3]);

            base = fmaf(k, pf.y, pb1);
            float inner = fmaf(k, pf.w, Am);
            pb1 = pf.z * inner;

            uint64_t kk; PACK64(kk, k, k);
            uint64_t p0, p1, p2, p3;
            MULX2(p0, rA[u & 3].x, kk); FMAX2(uu0, uu0, memm, p0);
            MULX2(p1, rA[u & 3].y, kk); FMAX2(uu1, uu1, memm, p1);
            MULX2(p2, rB[u & 3].x, kk); FMAX2(uu2, uu2, memm, p2);
            MULX2(p3, rB[u & 3].y, kk); FMAX2(uu3, uu3, memm, p3);

            const int cn = __ldg(lx + min(s + 4, S_LEN - 1));
            uint64_t sA = (cn & 2) ? uu1 : uu0;
            uint64_t sB = (cn & 2) ? uu3 : uu2;
            uint64_t sv = (cn & 4) ? sB : sA;
            float lo, hi; UNPACK64(lo, hi, sv);
            float v  = (cn & 1) ? hi : lo;
            float bc = __shfl_sync(0xffffffffu, v, cn >> 3);
            Am = mem * bc;

            const ulonglong2* rp = (const ulonglong2*)(tm + cn * NTASKS + lane * 8);
            rA[u & 3] = rp[0];
            rB[u & 3] = rp[1];
            PF[u & 7] = __ldg(prp + min(s + 8, S_LEN - 1));
        }
    }
}

// ---------------------------------------------------------------------------
// Out: 1024 blocks x 128 threads, one (algo, chunk) per block, seeded res.
// Per-thread 2-column recurrence + tanh + transposed coalesced stores.
// ---------------------------------------------------------------------------
__global__ void __launch_bounds__(128) idl_out(
    const int*   __restrict__ lx,
    const float* __restrict__ tm,
    const float* __restrict__ diff,
    const float* __restrict__ memA,
    float*       __restrict__ out)
{
    __shared__ float    kf_sh[CHUNK];
    __shared__ uint16_t t16_sh[CHUNK];
    __shared__ __align__(16) float sbuf[4][16][66];

    const int b    = blockIdx.x;
    const int a    = b >> 4;
    const int q    = b & 15;
    const int tid  = threadIdx.x;
    const int w    = tid >> 5;
    const int lane = tid & 31;
    const int s0   = q * CHUNK;

    // stage k and t-indices
    for (int i = tid; i < CHUNK; i += 128) {
        kf_sh[i]  = k_glob[b][i];
        t16_sh[i] = (uint16_t)(__ldg(lx + s0 + i) << 8);
    }
    __syncthreads();

    const int   c0  = w * 64 + 2 * lane;           // this thread's col pair
    const float mem = memA[a];
    const float wh0 = 0.5f * rcpf(__ldg(diff + c0));
    const float wh1 = 0.5f * rcpf(__ldg(diff + c0 + 1));
    uint64_t memm; PACK64(memm, mem, mem);

    const float2 seed = *(const float2*)&seed_glob[b][c0];
    uint64_t rr; PACK64(rr, seed.x, seed.y);

    #pragma unroll 1
    for (int tile = 0; tile < CHUNK / 16; tile++) {
        #pragma unroll
        for (int j = 0; j < 16; j++) {
            const int idx = tile * 16 + j;
            const uint32_t toff = (uint32_t)t16_sh[idx];
            uint64_t tv; LDG64(tv, (const void*)(tm + toff + c0));
            const float kv = kf_sh[idx];
            uint64_t kk; PACK64(kk, kv, kv);
            uint64_t pr; MULX2(pr, tv, kk);
            FMAX2(rr, rr, memm, pr);
            float lo, hi; UNPACK64(lo, hi, rr);
            float2 pair = make_float2(tanhapx(lo * wh0), tanhapx(hi * wh1));
            *(float2*)&sbuf[w][j][2 * lane] = pair;
        }
        __syncwarp();
        #pragma unroll
        for (int i2 = 0; i2 < 32; i2++) {
            const int cl = 2 * i2 + (lane >> 4);    // local col 0..63
            const int j  = lane & 15;
            const float v = sbuf[w][j][cl];
            out[(size_t)(a * NTASKS + w * 64 + cl) * (size_t)(S_LEN + 1)
                + 1 + s0 + tile * 16 + j] = v;
        }
        __syncwarp();
    }

    // zero output column 0 (once per algo)
    if (q == 0) {
        for (int c = tid; c < NTASKS; c += 128)
            out[(size_t)(a * NTASKS + c) * (size_t)(S_LEN + 1)] = 0.0f;
    }
}

extern "C" void kernel_launch(void* const* d_in, const int* in_sizes, int n_in,
                              void* d_out, int out_size)
{
    (void)in_sizes; (void)n_in; (void)out_size;
    const int*   lx    = (const int*)  d_in[0];
    const float* tm    = (const float*)d_in[1];
    const float* diff  = (const float*)d_in[2];
    const float* eff   = (const float*)d_in[3];
    const float* mem   = (const float*)d_in[4];
    const float* boost = (const float*)d_in[5];
    float*       out   = (float*)d_out;

    idl_prep<<<NALGOS * 32, 128>>>(lx, tm, diff, mem);
    idl_chain<<<NALGOS * NCHUNK, 32>>>(lx, tm, eff, mem, boost);
    idl_out<<<NALGOS * NCHUNK, 128>>>(lx, tm, diff, mem, out);
}